// round 6
// baseline (speedup 1.0000x reference)
#include <cuda_runtime.h>

// DerivativeDILATEloss: soft-DTW(gamma=0.01), D[i,j]=(dy_i-dx_j)^2, B=64, n=511.
//
// Round 6: register-tiled wavefront, W=4 rows/thread, 128 threads (4 warps).
// Thread t owns rows 4t..4t+3. Per diagonal step: ONE shfl pair (top-row
// boundary), ONE fresh dx LDS (rest shift through registers), 4 cells.
// R carried as (m,s), value = m - log2(s): 3 ex2/cell, no lg2 in the loop.
// Inter-warp boundary via full-length free-running smem (m,s) buffers.

#define NSEQ   511
#define NBATCH 64
#define NT     128
#define INFV   1.0e9f
#define INVK   0.0069314718055994531f  // ln(2)/100
#define SQRTK  12.011224298677374f     // sqrt(100/ln2)

__device__ __forceinline__ float ex2f(float x){float r;asm("ex2.approx.f32 %0,%1;":"=f"(r):"f"(x));return r;}
__device__ __forceinline__ float lg2f(float x){float r;asm("lg2.approx.f32 %0,%1;":"=f"(r):"f"(x));return r;}
__device__ __forceinline__ void st_rel(int* p, int v){
    unsigned a=(unsigned)__cvta_generic_to_shared(p);
    asm volatile("st.release.cta.shared.b32 [%0],%1;"::"r"(a),"r"(v):"memory");
}
__device__ __forceinline__ int ld_acq(const int* p){
    unsigned a=(unsigned)__cvta_generic_to_shared((void*)p); int v;
    asm volatile("ld.acquire.cta.shared.b32 %0,[%1];":"=r"(v):"r"(a):"memory");
    return v;
}

__device__ float g_partial[NBATCH];

__global__ __launch_bounds__(NT, 1)
void sdtw_kernel(const float* __restrict__ input,
                 const float* __restrict__ target)
{
    __shared__ float  sdxp[1536];      // padded scaled dx, logical base 512
    __shared__ int    cnt[4];
    __shared__ float2 bbuf[3][1024];   // boundary (m,s): warp w -> warp w+1

    const int b    = blockIdx.x;
    const int t    = threadIdx.x;
    const int w    = t >> 5;
    const int lane = t & 31;

    const float* in_b = input  + b * 512;
    const float* tg_b = target + b * 512;

    #pragma unroll
    for (int rep = 0; rep < 12; ++rep) {
        int idx = t + rep * NT;
        int q = idx - 512;
        float v = 0.0f;
        if (q >= 0 && q < NSEQ) v = (in_b[q + 1] - in_b[q]) * SQRTK;
        sdxp[idx] = v;
    }
    if (t < 4) cnt[t] = 0;

    const int i0 = 4 * t;              // rows i0..i0+3 (row 0 = DP boundary row)
    float dyr[4]; int dlo[4];
    #pragma unroll
    for (int k = 0; k < 4; ++k) {
        int i = i0 + k;
        dyr[k] = (i >= 1) ? (tg_b[i] - tg_b[i - 1]) * SQRTK : 0.0f;
        dlo[k] = (i >= 1) ? (i + 1) : (1 << 28);   // valid d window: [i+1, i+511]
    }
    __syncthreads();   // only CTA-wide barrier

    // (m,s) state: value = m - log2(s). r1 = diag d-1, r2 = diag d-2.
    float r1m[4], r1s[4], r2m[4], r2s[4];
    #pragma unroll
    for (int k = 0; k < 4; ++k) { r1m[k]=INFV; r1s[k]=1.0f; r2m[k]=INFV; r2s[k]=1.0f; }
    if (t == 0) r2m[0] = 0.0f;         // R[0,0] = 0
    float tn2m = INFV, tn2s = 1.0f;    // row i0-1 @ diag d-2
    float mbm  = INFV, mbs  = 1.0f;    // lane0 boundary: row i0-1 @ diag d-1
    int   cc   = 0;

    // dx register window: dxw[k] = dx[d - i0 - k - 1] (scaled), start d=2
    float dxw[4];
    #pragma unroll
    for (int k = 0; k < 4; ++k) dxw[k] = sdxp[512 + 1 - i0 - k];

    #pragma unroll 4
    for (int d = 2; d <= 2 * NSEQ; ++d) {
        float um = __shfl_up_sync(0xFFFFFFFFu, r1m[3], 1);  // row i0-1 @ d-1
        float us = __shfl_up_sync(0xFFFFFFFFu, r1s[3], 1);
        if (lane == 0) { um = mbm; us = mbs; }

        float nm[4], ns[4];
        {   // k = 0: neighbors from (tn2, um)
            const float am = tn2m, as_ = tn2s, em = um, es = us;
            const float cm = r1m[0], cs = r1s[0];
            const float mm = fminf(fminf(am, em), cm);
            const float s  = as_ * ex2f(mm - am) + es * ex2f(mm - em) + cs * ex2f(mm - cm);
            const float dv = dyr[0] - dxw[0];
            const float m  = fmaf(dv, dv, mm);
            const bool valid = ((unsigned)(d - dlo[0]) <= 510u);
            nm[0] = valid ? m : INFV;  ns[0] = valid ? s : 1.0f;
        }
        #pragma unroll
        for (int k = 1; k < 4; ++k) {
            const float am = r2m[k-1], as_ = r2s[k-1];
            const float em = r1m[k-1], es = r1s[k-1];
            const float cm = r1m[k],   cs = r1s[k];
            const float mm = fminf(fminf(am, em), cm);
            const float s  = as_ * ex2f(mm - am) + es * ex2f(mm - em) + cs * ex2f(mm - cm);
            const float dv = dyr[k] - dxw[k];
            const float m  = fmaf(dv, dv, mm);
            const bool valid = ((unsigned)(d - dlo[k]) <= 510u);
            nm[k] = valid ? m : INFV;  ns[k] = valid ? s : 1.0f;
        }

        if ((d & 3) == 0) {   // exact power-of-2 renorm of s into m
            #pragma unroll
            for (int k = 0; k < 4; ++k) {
                unsigned sb = __float_as_uint(ns[k]);
                int e = (int)(sb >> 23) - 127;
                ns[k] = __uint_as_float((sb & 0x007FFFFFu) | 0x3F800000u);
                nm[k] -= (float)e;
            }
        }

        // publish bottom row (warps 0..2)
        if (w < 3 && lane == 31) {
            bbuf[w][d] = make_float2(nm[3], ns[3]);
            if ((d & 3) == 0 || d == 2 * NSEQ) st_rel(&cnt[w], d);
        }
        // prefetch boundary slot d (used at step d+1) — warps 1..3, all lanes
        if (w >= 1) {
            if (cc < d) { do { cc = ld_acq(&cnt[w - 1]); } while (cc < d); }
            float2 bn = bbuf[w - 1][d];
            mbm = bn.x; mbs = bn.y;
        }

        // rotate state
        tn2m = um; tn2s = us;
        #pragma unroll
        for (int k = 0; k < 4; ++k) { r2m[k]=r1m[k]; r2s[k]=r1s[k]; r1m[k]=nm[k]; r1s[k]=ns[k]; }
        dxw[3] = dxw[2]; dxw[2] = dxw[1]; dxw[1] = dxw[0];
        dxw[0] = sdxp[512 + d - i0];   // dx for row i0 at step d+1
    }

    // thread 127, k=3 holds R[511,511] as (m,s)
    if (t == NT - 1) g_partial[b] = (r1m[3] - lg2f(r1s[3])) * INVK;
}

__global__ void reduce_kernel(float* __restrict__ out)
{
    const int l = threadIdx.x;
    float s = g_partial[l] + g_partial[l + 32];
    #pragma unroll
    for (int o = 16; o > 0; o >>= 1)
        s += __shfl_down_sync(0xFFFFFFFFu, s, o);
    if (l == 0) out[0] = s * (1.0f / (float)NBATCH);
}

extern "C" void kernel_launch(void* const* d_in, const int* in_sizes, int n_in,
                              void* d_out, int out_size)
{
    const float* input  = (const float*)d_in[0];
    const float* target = (const float*)d_in[1];
    float* out = (float*)d_out;

    sdtw_kernel<<<NBATCH, NT>>>(input, target);
    reduce_kernel<<<1, 32>>>(out);
}

// round 7
// speedup vs baseline: 1.2687x; 1.2687x over previous
#include <cuda_runtime.h>

// DerivativeDILATEloss: soft-DTW(gamma=0.01), D[i,j]=(dy_i-dx_j)^2, B=64, n=511.
//
// Round 7: branchless register-tiled wavefront. 128 threads (4 warps), thread
// t owns rows 4t..4t+3. (m,s) representation, 2 ex2/cell via branchless
// 3-way pair sort. Publish = single float (m - lg2 s) via PREDICATED asm STS
// (no BSSY). Consumer poll once per 4-step block. Renorm/counter at
// compile-time body 3. Fused last-CTA reduction (single kernel launch).

#define NSEQ   511
#define NBATCH 64
#define NT     128
#define INFV   1.0e9f
#define INVK   0.0069314718055994531f  // ln(2)/100
#define SQRTK  12.011224298677374f     // sqrt(100/ln2)

__device__ __forceinline__ float ex2f(float x){float r;asm("ex2.approx.f32 %0,%1;":"=f"(r):"f"(x));return r;}
__device__ __forceinline__ float lg2f(float x){float r;asm("lg2.approx.f32 %0,%1;":"=f"(r):"f"(x));return r;}
__device__ __forceinline__ unsigned s2u(const void* p){return (unsigned)__cvta_generic_to_shared(p);}
__device__ __forceinline__ void sts_pred(unsigned a, float v, int p){
    asm volatile("{.reg .pred q; setp.ne.u32 q,%0,0; @q st.shared.f32 [%1],%2;}"
                 ::"r"(p),"r"(a),"f"(v):"memory");
}
__device__ __forceinline__ void strel_pred(unsigned a, int v, int p){
    asm volatile("{.reg .pred q; setp.ne.u32 q,%0,0; @q st.release.cta.shared.b32 [%1],%2;}"
                 ::"r"(p),"r"(a),"r"(v):"memory");
}
__device__ __forceinline__ int ld_acq(unsigned a){
    int v; asm volatile("ld.acquire.cta.shared.b32 %0,[%1];":"=r"(v):"r"(a):"memory"); return v;
}

__device__ float g_partial[NBATCH];
__device__ int   g_done = 0;

// one diagonal step for 4 rows (k=0 uses (tn2, um/us) as upper neighbors)
#define CELL(k, AM, AS, EM, ES)                                              \
    {                                                                        \
        const float cm = r1m[k], cs = r1s[k];                                \
        const bool  pe = ((EM) < (AM));                                      \
        const float l1m = pe ? (EM) : (AM), l1s = pe ? (ES) : (AS);          \
        const float h1m = pe ? (AM) : (EM), h1s = pe ? (AS) : (ES);          \
        const bool  pc = (cm < l1m);                                         \
        const float mnm = pc ? cm : l1m, mns = pc ? cs : l1s;                \
        const float o1m = pc ? l1m : cm, o1s = pc ? l1s : cs;                \
        const float s = fmaf(o1s, ex2f(mnm - o1m),                           \
                        fmaf(h1s, ex2f(mnm - h1m), mns));                    \
        const float dv = dyr[k] - dxw[k];                                    \
        const float m  = fmaf(dv, dv, mnm);                                  \
        const bool valid = ((unsigned)(d - dlo[k]) <= 510u);                 \
        nm[k] = valid ? m : INFV;                                            \
        ns[k] = valid ? s : 1.0f;                                            \
    }

__global__ __launch_bounds__(NT, 1)
void sdtw_kernel(const float* __restrict__ input,
                 const float* __restrict__ target,
                 float* __restrict__ out)
{
    __shared__ float sdxp[1536];       // padded scaled dx, logical base 512
    __shared__ float bbuf[5][1024];    // boundary v per warp; row 4 = dummy
    __shared__ int   cnt[8];           // [0..3] progress, [7] = +inf sentinel
    __shared__ int   slast;

    const int b = blockIdx.x, t = threadIdx.x, w = t >> 5, lane = t & 31;
    const float* in_b = input  + b * 512;
    const float* tg_b = target + b * 512;

    #pragma unroll
    for (int rep = 0; rep < 12; ++rep) {
        int idx = t + rep * NT, q = idx - 512;
        float v = 0.0f;
        if (q >= 0 && q < NSEQ) v = (in_b[q + 1] - in_b[q]) * SQRTK;
        sdxp[idx] = v;
    }
    #pragma unroll
    for (int rep = 0; rep < 8; ++rep) bbuf[4][t + rep * NT] = INFV;
    if (t < 8) cnt[t] = (t == 7) ? 0x7FFFFFFF : 0;

    const int i0 = 4 * t;
    float dyr[4]; int dlo[4];
    #pragma unroll
    for (int k = 0; k < 4; ++k) {
        int i = i0 + k;
        dyr[k] = (i >= 1) ? (tg_b[i] - tg_b[i - 1]) * SQRTK : 0.0f;
        dlo[k] = (i >= 1) ? (i + 1) : (1 << 28);
    }
    __syncthreads();   // only CTA-wide barrier

    float r1m[4], r1s[4], r2m[4], r2s[4];
    #pragma unroll
    for (int k = 0; k < 4; ++k) { r1m[k]=INFV; r1s[k]=1.0f; r2m[k]=INFV; r2s[k]=1.0f; }
    if (t == 0) r2m[0] = 0.0f;                 // R[0,0] = 0
    float tn2m = INFV, tn2s = 1.0f, mbm = INFV;
    float dxw[4];
    #pragma unroll
    for (int k = 0; k < 4; ++k) dxw[k] = sdxp[512 + 1 - i0 - k];

    const float* subrow = bbuf[(w == 0) ? 4 : (w - 1)];
    unsigned pub_a  = s2u(&bbuf[w][0]) + 2u * 4u;
    unsigned cnt_a  = s2u(&cnt[w]);
    unsigned cntp_a = s2u(&cnt[(w == 0) ? 7 : (w - 1)]);
    const int ispub = (lane == 31 && w < 3) ? 1 : 0;
    int cc = 0;
    const float* dxsrc = sdxp + 512 - i0;

    #pragma unroll 1
    for (int d0 = 2; d0 <= 1018; d0 += 4) {
        const int need = d0 + 3;
        if (cc < need) { do { cc = ld_acq(cntp_a); } while (cc < need); }

        #pragma unroll
        for (int u = 0; u < 4; ++u) {
            const int d = d0 + u;
            const float bn = subrow[d];                    // for step d+1
            const float shm = __shfl_up_sync(0xFFFFFFFFu, r1m[3], 1);
            const float shs = __shfl_up_sync(0xFFFFFFFFu, r1s[3], 1);
            const float um = (lane == 0) ? mbm  : shm;
            const float us = (lane == 0) ? 1.0f : shs;

            float nm[4], ns[4];
            CELL(0, tn2m,   tn2s,   um,     us)
            CELL(1, r2m[0], r2s[0], r1m[0], r1s[0])
            CELL(2, r2m[1], r2s[1], r1m[1], r1s[1])
            CELL(3, r2m[2], r2s[2], r1m[2], r1s[2])

            if (u == 3) {   // exact power-of-2 renorm of s into m
                #pragma unroll
                for (int k = 0; k < 4; ++k) {
                    unsigned sb = __float_as_uint(ns[k]);
                    int e = (int)(sb >> 23) - 127;
                    ns[k] = __uint_as_float((sb & 0x007FFFFFu) | 0x3F800000u);
                    nm[k] -= (float)e;
                }
            }

            const float v31 = nm[3] - lg2f(ns[3]);         // boundary value
            sts_pred(pub_a, v31, ispub);
            if (u == 3) strel_pred(cnt_a, d, ispub);
            pub_a += 4u;

            tn2m = um; tn2s = us;
            #pragma unroll
            for (int k = 0; k < 4; ++k) { r2m[k]=r1m[k]; r2s[k]=r1s[k]; r1m[k]=nm[k]; r1s[k]=ns[k]; }
            dxw[3]=dxw[2]; dxw[2]=dxw[1]; dxw[1]=dxw[0];
            dxw[0] = dxsrc[d];
            mbm = bn;
        }
    }

    // tail step d = 1022 (no publish/poll)
    float resm, ress;
    {
        const int d = 1022;
        const float shm = __shfl_up_sync(0xFFFFFFFFu, r1m[3], 1);
        const float shs = __shfl_up_sync(0xFFFFFFFFu, r1s[3], 1);
        const float um = (lane == 0) ? mbm  : shm;
        const float us = (lane == 0) ? 1.0f : shs;
        float nm[4], ns[4];
        CELL(0, tn2m,   tn2s,   um,     us)
        CELL(1, r2m[0], r2s[0], r1m[0], r1s[0])
        CELL(2, r2m[1], r2s[1], r1m[1], r1s[1])
        CELL(3, r2m[2], r2s[2], r1m[2], r1s[2])
        resm = nm[3]; ress = ns[3];
    }

    // fused reduction: last CTA sums g_partial and writes out
    if (t == NT - 1) {
        g_partial[b] = (resm - lg2f(ress)) * INVK;
        __threadfence();
        int prev = atomicAdd(&g_done, 1);
        slast = (prev == NBATCH - 1) ? 1 : 0;
    }
    __syncthreads();
    if (slast && t < 32) {
        __threadfence();
        float s = g_partial[t] + g_partial[t + 32];
        #pragma unroll
        for (int o = 16; o > 0; o >>= 1)
            s += __shfl_down_sync(0xFFFFFFFFu, s, o);
        if (t == 0) { out[0] = s * (1.0f / (float)NBATCH); g_done = 0; }
    }
}

extern "C" void kernel_launch(void* const* d_in, const int* in_sizes, int n_in,
                              void* d_out, int out_size)
{
    const float* input  = (const float*)d_in[0];
    const float* target = (const float*)d_in[1];
    float* out = (float*)d_out;

    sdtw_kernel<<<NBATCH, NT>>>(input, target, out);
}

// round 8
// speedup vs baseline: 1.5478x; 1.2199x over previous
#include <cuda_runtime.h>

// DerivativeDILATEloss: soft-DTW(gamma=0.01), D[i,j]=(dy_i-dx_j)^2, B=64, n=511.
//
// Round 8: W=2 rows/thread, 256 threads (8 warps -> 2 warps/SMSP for latency
// hiding). (m,s) representation, 2 ex2/cell via branchless pair sort; NO lg2
// in the loop (boundary published as (m,s) float2). Validity via dx padding
// (1e4 -> dv^2 ~ 1e8 acts as INF), no per-cell valid SELs. Free-running
// full-length inter-warp mailboxes in dynamic smem. Fused last-CTA reduction.

#define NSEQ   511
#define NBATCH 64
#define NT     256
#define INFV   1.0e9f
#define PADV   1.0e4f
#define INVK   0.0069314718055994531f  // ln(2)/100
#define SQRTK  12.011224298677374f     // sqrt(100/ln2)

// dynamic smem: float2 bbuf[8][1024]  (rows 0..6 producers, row 7 dummy)
#define SMEM_BYTES (8 * 1024 * 8)

__device__ __forceinline__ float ex2f(float x){float r;asm("ex2.approx.f32 %0,%1;":"=f"(r):"f"(x));return r;}
__device__ __forceinline__ float lg2f(float x){float r;asm("lg2.approx.f32 %0,%1;":"=f"(r):"f"(x));return r;}
__device__ __forceinline__ unsigned s2u(const void* p){return (unsigned)__cvta_generic_to_shared(p);}
__device__ __forceinline__ void sts_pair_pred(unsigned a, float m, float s, int p){
    asm volatile("{.reg .pred q; setp.ne.u32 q,%0,0; @q st.shared.v2.f32 [%1],{%2,%3};}"
                 ::"r"(p),"r"(a),"f"(m),"f"(s):"memory");
}
__device__ __forceinline__ void strel_pred(unsigned a, int v, int p){
    asm volatile("{.reg .pred q; setp.ne.u32 q,%0,0; @q st.release.cta.shared.b32 [%1],%2;}"
                 ::"r"(p),"r"(a),"r"(v):"memory");
}
__device__ __forceinline__ int ld_acq(unsigned a){
    int v; asm volatile("ld.acquire.cta.shared.b32 %0,[%1];":"=r"(v):"r"(a):"memory"); return v;
}

__device__ float g_partial[NBATCH];
__device__ int   g_done = 0;

// one cell: value = m - log2(s); neighbors (A = diag d-2 corner, E = up, C = left)
#define CELL(NM, NS, AM, AS, EM, ES, CM, CS, DY, DX)                         \
    {                                                                        \
        const bool  pe = ((EM) < (AM));                                      \
        const float l1m = pe ? (EM) : (AM), l1s = pe ? (ES) : (AS);          \
        const float h1m = pe ? (AM) : (EM), h1s = pe ? (AS) : (ES);          \
        const bool  pc = ((CM) < l1m);                                       \
        const float mnm = pc ? (CM) : l1m, mns = pc ? (CS) : l1s;            \
        const float o1m = pc ? l1m : (CM), o1s = pc ? l1s : (CS);            \
        NS = fmaf(o1s, ex2f(mnm - o1m), fmaf(h1s, ex2f(mnm - h1m), mns));    \
        const float dv = (DY) - (DX);                                        \
        NM = fmaf(dv, dv, mnm);                                              \
    }

__global__ __launch_bounds__(NT, 1)
void sdtw_kernel(const float* __restrict__ input,
                 const float* __restrict__ target,
                 float* __restrict__ out)
{
    __shared__ float sdxp[1536];   // padded scaled dx, logical base 512
    __shared__ int   cnt[16];      // [0..7] progress, [15] = +inf sentinel
    __shared__ int   slast;
    extern __shared__ float2 bbuf[];   // [8][1024]

    const int b = blockIdx.x, t = threadIdx.x, w = t >> 5, lane = t & 31;
    const float* in_b = input  + b * 512;
    const float* tg_b = target + b * 512;

    #pragma unroll
    for (int rep = 0; rep < 6; ++rep) {
        int idx = t + rep * NT, q = idx - 512;
        float v = PADV;
        if (q >= 0 && q < NSEQ) v = (in_b[q + 1] - in_b[q]) * SQRTK;
        sdxp[idx] = v;
    }
    #pragma unroll
    for (int rep = 0; rep < 4; ++rep)          // dummy row 7: (INF, 1)
        bbuf[7 * 1024 + t + rep * NT] = make_float2(INFV, 1.0f);
    if (t < 16) cnt[t] = (t == 15) ? 0x7FFFFFFF : 0;

    const int i0 = 2 * t;                      // rows i0, i0+1
    float dyr[2];
    #pragma unroll
    for (int k = 0; k < 2; ++k) {
        int i = i0 + k;
        dyr[k] = (i >= 1) ? (tg_b[i] - tg_b[i - 1]) * SQRTK : 0.0f;
    }
    __syncthreads();   // only CTA-wide barrier

    // state (m,s): r1 = diag d-1, r2 = diag d-2, per owned row
    float r1m0 = INFV, r1s0 = 1.0f, r1m1 = INFV, r1s1 = 1.0f;
    float r2m0 = INFV, r2s0 = 1.0f, r2m1 = INFV, r2s1 = 1.0f;
    if (t == 0) r2m0 = 0.0f;                   // R[0,0] = 0
    float tn2m = INFV, tn2s = 1.0f;            // row i0-1 @ diag d-2
    float mbm  = INFV, mbs  = 1.0f;            // lane-0 boundary @ diag d-1
    float dxw0 = sdxp[512 + 1 - i0];           // dx[d-i0-1] @ d=2
    float dxw1 = sdxp[512 - i0];               // dx[d-i0-2] @ d=2

    const float2* subrow = bbuf + ((w == 0) ? 7 : (w - 1)) * 1024;
    unsigned pub_a  = s2u(&bbuf[w * 1024]) + 2u * 8u;
    unsigned cnt_a  = s2u(&cnt[w]);
    unsigned cntp_a = s2u(&cnt[(w == 0) ? 15 : (w - 1)]);
    const int ispub = (lane == 31 && w < 7) ? 1 : 0;
    int cc = 0;
    const float* dxsrc = sdxp + 512 - i0;

    #pragma unroll 1
    for (int d0 = 2; d0 <= 1018; d0 += 4) {
        const int need = d0 + 3;
        if (cc < need) { do { cc = ld_acq(cntp_a); } while (cc < need); }

        #pragma unroll
        for (int u = 0; u < 4; ++u) {
            const int d = d0 + u;
            const float2 bn = subrow[d];                  // for step d+1
            const float shm = __shfl_up_sync(0xFFFFFFFFu, r1m1, 1);
            const float shs = __shfl_up_sync(0xFFFFFFFFu, r1s1, 1);
            const float um = (lane == 0) ? mbm : shm;
            const float us = (lane == 0) ? mbs : shs;

            float nm0, ns0, nm1, ns1;
            CELL(nm0, ns0, tn2m, tn2s, um,   us,   r1m0, r1s0, dyr[0], dxw0)
            CELL(nm1, ns1, r2m0, r2s0, r1m0, r1s0, r1m1, r1s1, dyr[1], dxw1)

            if (u == 3) {   // exact power-of-2 renorm of s into m
                unsigned sb0 = __float_as_uint(ns0);
                int e0 = (int)(sb0 >> 23) - 127;
                ns0 = __uint_as_float((sb0 & 0x007FFFFFu) | 0x3F800000u);
                nm0 -= (float)e0;
                unsigned sb1 = __float_as_uint(ns1);
                int e1 = (int)(sb1 >> 23) - 127;
                ns1 = __uint_as_float((sb1 & 0x007FFFFFu) | 0x3F800000u);
                nm1 -= (float)e1;
            }

            sts_pair_pred(pub_a, nm1, ns1, ispub);        // slot d
            if (u == 3) strel_pred(cnt_a, d, ispub);
            pub_a += 8u;

            tn2m = um;  tn2s = us;
            r2m0 = r1m0; r2s0 = r1s0; r2m1 = r1m1; r2s1 = r1s1;
            r1m0 = nm0;  r1s0 = ns0;  r1m1 = nm1;  r1s1 = ns1;
            dxw1 = dxw0;
            dxw0 = dxsrc[d];                               // dx for step d+1
            mbm = bn.x; mbs = bn.y;
        }
    }

    // tail step d = 1022 (no publish/poll)
    float resm, ress;
    {
        const float shm = __shfl_up_sync(0xFFFFFFFFu, r1m1, 1);
        const float shs = __shfl_up_sync(0xFFFFFFFFu, r1s1, 1);
        const float um = (lane == 0) ? mbm : shm;
        const float us = (lane == 0) ? mbs : shs;
        float nm0, ns0, nm1, ns1;
        CELL(nm0, ns0, tn2m, tn2s, um,   us,   r1m0, r1s0, dyr[0], dxw0)
        CELL(nm1, ns1, r2m0, r2s0, r1m0, r1s0, r1m1, r1s1, dyr[1], dxw1)
        (void)nm0; (void)ns0;
        resm = nm1; ress = ns1;
    }

    // fused reduction: last CTA sums g_partial and writes out
    if (t == NT - 1) {
        g_partial[b] = (resm - lg2f(ress)) * INVK;
        __threadfence();
        int prev = atomicAdd(&g_done, 1);
        slast = (prev == NBATCH - 1) ? 1 : 0;
    }
    __syncthreads();
    if (slast && t < 32) {
        __threadfence();
        float s = g_partial[t] + g_partial[t + 32];
        #pragma unroll
        for (int o = 16; o > 0; o >>= 1)
            s += __shfl_down_sync(0xFFFFFFFFu, s, o);
        if (t == 0) { out[0] = s * (1.0f / (float)NBATCH); g_done = 0; }
    }
}

extern "C" void kernel_launch(void* const* d_in, const int* in_sizes, int n_in,
                              void* d_out, int out_size)
{
    const float* input  = (const float*)d_in[0];
    const float* target = (const float*)d_in[1];
    float* out = (float*)d_out;

    cudaFuncSetAttribute(sdtw_kernel,
                         cudaFuncAttributeMaxDynamicSharedMemorySize, SMEM_BYTES);
    sdtw_kernel<<<NBATCH, NT, SMEM_BYTES>>>(input, target, out);
}

// round 10
// speedup vs baseline: 1.7670x; 1.1416x over previous
#include <cuda_runtime.h>

// DerivativeDILATEloss: soft-DTW(gamma=0.01), D[i,j]=(dy_i-dx_j)^2, B=64, n=511.
//
// Round 10 (= R9 + compile fix: template-constant STS offset). W=2 rows/thread,
// 256 threads (2 warps/SMSP). Direct 3-ex2 softmin in (m,s) form. Boundary
// mailbox read via 2x LDS.128 per 4-step block; publish via predicated STS
// with immediate offsets. dx padding (1e4) replaces validity selects.
// Free-running full-length inter-warp mailboxes; fused last-CTA reduction.

#define NSEQ   511
#define NBATCH 64
#define NT     256
#define INFV   1.0e9f
#define PADV   1.0e4f
#define INVK   0.0069314718055994531f  // ln(2)/100
#define SQRTK  12.011224298677374f     // sqrt(100/ln2)

// dynamic smem: float2 bbuf[8][1024]  (rows 0..6 producers, row 7 dummy)
#define SMEM_BYTES (8 * 1024 * 8)

__device__ __forceinline__ float ex2f(float x){float r;asm("ex2.approx.f32 %0,%1;":"=f"(r):"f"(x));return r;}
__device__ __forceinline__ float lg2f(float x){float r;asm("lg2.approx.f32 %0,%1;":"=f"(r):"f"(x));return r;}
__device__ __forceinline__ unsigned s2u(const void* p){return (unsigned)__cvta_generic_to_shared(p);}
template<int OFF>
__device__ __forceinline__ void sts_pair_pred_off(unsigned a, float m, float s, int p){
    asm volatile("{.reg .pred q; setp.ne.u32 q,%0,0; @q st.shared.v2.f32 [%1+%4],{%2,%3};}"
                 ::"r"(p),"r"(a),"f"(m),"f"(s),"n"(OFF):"memory");
}
__device__ __forceinline__ void strel_pred(unsigned a, int v, int p){
    asm volatile("{.reg .pred q; setp.ne.u32 q,%0,0; @q st.release.cta.shared.b32 [%1],%2;}"
                 ::"r"(p),"r"(a),"r"(v):"memory");
}
__device__ __forceinline__ int ld_acq(unsigned a){
    int v; asm volatile("ld.acquire.cta.shared.b32 %0,[%1];":"=r"(v):"r"(a):"memory"); return v;
}

__device__ float g_partial[NBATCH];
__device__ int   g_done = 0;

// one cell, (m,s) form (value = m - log2 s), direct 3-ex2 softmin.
// "INF" = 1e9 is finite: INF-INF = 0 -> ex2(0)=1, no NaNs; real gaps underflow to 0.
#define CELL(NM, NS, AM, AS, EM, ES, CM, CS, DY, DX)                         \
    {                                                                        \
        const float mnm = fminf(fminf((AM), (EM)), (CM));                    \
        const float x1 = ex2f(mnm - (AM));                                   \
        const float x2 = ex2f(mnm - (EM));                                   \
        const float x3 = ex2f(mnm - (CM));                                   \
        NS = fmaf((AS), x1, fmaf((ES), x2, (CS) * x3));                      \
        const float dv = (DY) - (DX);                                        \
        NM = fmaf(dv, dv, mnm);                                              \
    }

__global__ __launch_bounds__(NT, 1)
void sdtw_kernel(const float* __restrict__ input,
                 const float* __restrict__ target,
                 float* __restrict__ out)
{
    __shared__ float sdxp[1536];   // padded scaled dx, logical base 512
    __shared__ int   cnt[16];      // [0..7] progress, [15] = +inf sentinel
    __shared__ int   slast;
    extern __shared__ float2 bbuf[];   // [8][1024]

    const int b = blockIdx.x, t = threadIdx.x, w = t >> 5, lane = t & 31;
    const float* in_b = input  + b * 512;
    const float* tg_b = target + b * 512;

    #pragma unroll
    for (int rep = 0; rep < 6; ++rep) {
        int idx = t + rep * NT, q = idx - 512;
        float v = PADV;
        if (q >= 0 && q < NSEQ) v = (in_b[q + 1] - in_b[q]) * SQRTK;
        sdxp[idx] = v;
    }
    #pragma unroll
    for (int rep = 0; rep < 4; ++rep)          // dummy row 7: (INF, 1)
        bbuf[7 * 1024 + t + rep * NT] = make_float2(INFV, 1.0f);
    if (t < 16) cnt[t] = (t == 15) ? 0x7FFFFFFF : 0;

    const int i0 = 2 * t;                      // rows i0, i0+1
    float dyr0, dyr1;
    dyr0 = (i0     >= 1) ? (tg_b[i0]     - tg_b[i0 - 1]) * SQRTK : 0.0f;
    dyr1 =                 (tg_b[i0 + 1] - tg_b[i0])     * SQRTK;
    __syncthreads();   // only CTA-wide barrier

    // state (m,s): r1 = diag d-1, r2 = diag d-2, per owned row
    float r1m0 = INFV, r1s0 = 1.0f, r1m1 = INFV, r1s1 = 1.0f;
    float r2m0 = INFV, r2s0 = 1.0f;
    if (t == 0) r2m0 = 0.0f;                   // R[0,0] = 0
    float tn2m = INFV, tn2s = 1.0f;            // row i0-1 @ diag d-2
    float mbm  = INFV, mbs  = 1.0f;            // lane-0 boundary @ diag d-1
    float dxw0 = sdxp[512 + 1 - i0];           // dx[d-i0-1] @ d=2
    float dxw1 = sdxp[512 - i0];               // dx[d-i0-2] @ d=2

    const float2* subrow = bbuf + ((w == 0) ? 7 : (w - 1)) * 1024;
    unsigned pub_a  = s2u(&bbuf[w * 1024]) + 2u * 8u;   // slot d0=2
    unsigned cnt_a  = s2u(&cnt[w]);
    unsigned cntp_a = s2u(&cnt[(w == 0) ? 15 : (w - 1)]);
    const int ispub = (lane == 31 && w < 7) ? 1 : 0;
    int cc = 0;
    const float* dxsrc = sdxp + 512 - i0;

    #pragma unroll 1
    for (int d0 = 2; d0 <= 1018; d0 += 4) {
        const int need = d0 + 3;
        if (cc < need) { do { cc = ld_acq(cntp_a); } while (cc < need); }

        // batched boundary fetch: slots d0..d0+3 (consumed at steps d0+1..)
        const float4 bl0 = *reinterpret_cast<const float4*>(subrow + d0);
        const float4 bl1 = *reinterpret_cast<const float4*>(subrow + d0 + 2);

        #pragma unroll
        for (int u = 0; u < 4; ++u) {
            const int d = d0 + u;
            const float shm = __shfl_up_sync(0xFFFFFFFFu, r1m1, 1);
            const float shs = __shfl_up_sync(0xFFFFFFFFu, r1s1, 1);
            const float um = (lane == 0) ? mbm : shm;
            const float us = (lane == 0) ? mbs : shs;

            float nm0, ns0, nm1, ns1;
            CELL(nm0, ns0, tn2m, tn2s, um,   us,   r1m0, r1s0, dyr0, dxw0)
            CELL(nm1, ns1, r2m0, r2s0, r1m0, r1s0, r1m1, r1s1, dyr1, dxw1)

            if (u == 3) {   // exact power-of-2 renorm of s into m
                unsigned sb0 = __float_as_uint(ns0);
                int e0 = (int)(sb0 >> 23) - 127;
                ns0 = __uint_as_float((sb0 & 0x007FFFFFu) | 0x3F800000u);
                nm0 -= (float)e0;
                unsigned sb1 = __float_as_uint(ns1);
                int e1 = (int)(sb1 >> 23) - 127;
                ns1 = __uint_as_float((sb1 & 0x007FFFFFu) | 0x3F800000u);
                nm1 -= (float)e1;
            }

            if (u == 0) sts_pair_pred_off<0 >(pub_a, nm1, ns1, ispub);
            if (u == 1) sts_pair_pred_off<8 >(pub_a, nm1, ns1, ispub);
            if (u == 2) sts_pair_pred_off<16>(pub_a, nm1, ns1, ispub);
            if (u == 3) sts_pair_pred_off<24>(pub_a, nm1, ns1, ispub);
            if (u == 3) strel_pred(cnt_a, d, ispub);

            tn2m = um;  tn2s = us;
            r2m0 = r1m0; r2s0 = r1s0;
            r1m0 = nm0;  r1s0 = ns0;  r1m1 = nm1;  r1s1 = ns1;
            dxw1 = dxw0;
            dxw0 = dxsrc[d];                               // dx for step d+1
            mbm = (u == 0) ? bl0.x : (u == 1) ? bl0.z : (u == 2) ? bl1.x : bl1.z;
            mbs = (u == 0) ? bl0.y : (u == 1) ? bl0.w : (u == 2) ? bl1.y : bl1.w;
        }
        pub_a += 32u;
    }

    // tail step d = 1022 (no publish/poll)
    float resm, ress;
    {
        const float shm = __shfl_up_sync(0xFFFFFFFFu, r1m1, 1);
        const float shs = __shfl_up_sync(0xFFFFFFFFu, r1s1, 1);
        const float um = (lane == 0) ? mbm : shm;
        const float us = (lane == 0) ? mbs : shs;
        float nm1, ns1;
        CELL(nm1, ns1, r2m0, r2s0, r1m0, r1s0, r1m1, r1s1, dyr1, dxw1)
        (void)um; (void)us;
        resm = nm1; ress = ns1;
    }

    // fused reduction: last CTA sums g_partial and writes out
    if (t == NT - 1) {
        g_partial[b] = (resm - lg2f(ress)) * INVK;
        __threadfence();
        int prev = atomicAdd(&g_done, 1);
        slast = (prev == NBATCH - 1) ? 1 : 0;
    }
    __syncthreads();
    if (slast && t < 32) {
        __threadfence();
        float s = g_partial[t] + g_partial[t + 32];
        #pragma unroll
        for (int o = 16; o > 0; o >>= 1)
            s += __shfl_down_sync(0xFFFFFFFFu, s, o);
        if (t == 0) { out[0] = s * (1.0f / (float)NBATCH); g_done = 0; }
    }
}

extern "C" void kernel_launch(void* const* d_in, const int* in_sizes, int n_in,
                              void* d_out, int out_size)
{
    const float* input  = (const float*)d_in[0];
    const float* target = (const float*)d_in[1];
    float* out = (float*)d_out;

    cudaFuncSetAttribute(sdtw_kernel,
                         cudaFuncAttributeMaxDynamicSharedMemorySize, SMEM_BYTES);
    sdtw_kernel<<<NBATCH, NT, SMEM_BYTES>>>(input, target, out);
}